// round 6
// baseline (speedup 1.0000x reference)
#include <cuda_runtime.h>
#include <cuda_fp16.h>
#include <cstdint>
#include <math.h>

// ============================================================================
// VectorQuantizer — base-target ISA only (mma.sync m16n8k16 + cp.async).
//   N = 262144 rows, D = 64, K = 1024 codes.
//   key_k = dot(xn, cn_k) - 0.5*||cn_k||^2   (argmax == reference argmin)
//   fp16 HMMA scores + per-row top-12 candidates + fp64 rescue of tight rows.
// ============================================================================

#define NROWS   262144
#define DIM     64
#define KCODES  1024
#define NQ      16777216
#define TILES   2048
#define THRESH  2e-3f

// ---- device scratch ----
__device__ __align__(16) __half  g_bh[KCODES * DIM];   // normalized codebook fp16
__device__ __align__(16) float   g_cnf[KCODES * DIM];  // normalized codebook fp32
__device__ double                g_biasd[KCODES];      // 0.5*||cn||^2 fp64
__device__ float                 g_biasf[KCODES];      // 0.5*||cn||^2 fp32
__device__ float                 g_partials[TILES];

// ---- smem layout (bytes) ----
#define SM_XS    0          // 128 x 68 floats           = 34816
#define SM_A     34816      // 128 x 72 halfs (144B)     = 18432
#define SM_B     53248      // 2 x 128 x 72 halfs        = 36864
#define SM_BIAS  90112      // 1024 floats               = 4096
#define SM_RN    94208      // 128 floats                = 512
#define SM_CAND  94720      // 128 x 12 ints             = 6144
#define SM_LIST  100864     // 128 ints                  = 512
#define SM_CNT   101376     // 1 int (pad 16)            = 16
#define SM_ISW   101392     // 128 ints                  = 512
#define SM_RED   101904     // 8 floats                  = 32
#define SM_TOTAL 101952

// ---- PTX helpers ----
__device__ __forceinline__ void mma16816(float c[4], const uint32_t a[4],
                                         uint32_t b0, uint32_t b1) {
    asm volatile(
        "mma.sync.aligned.m16n8k16.row.col.f32.f16.f16.f32 "
        "{%0,%1,%2,%3}, {%4,%5,%6,%7}, {%8,%9}, {%0,%1,%2,%3};"
        : "+f"(c[0]), "+f"(c[1]), "+f"(c[2]), "+f"(c[3])
        : "r"(a[0]), "r"(a[1]), "r"(a[2]), "r"(a[3]), "r"(b0), "r"(b1));
}
__device__ __forceinline__ uint32_t smem_u32(const void* p) {
    uint32_t a;
    asm("{ .reg .u64 t; cvta.to.shared.u64 t, %1; cvt.u32.u64 %0, t; }"
        : "=r"(a) : "l"(p));
    return a;
}
__device__ __forceinline__ void cp16(uint32_t dst, const void* src) {
    asm volatile("cp.async.cg.shared.global [%0], [%1], 16;"
                 :: "r"(dst), "l"(src) : "memory");
}
__device__ __forceinline__ void cp_commit() {
    asm volatile("cp.async.commit_group;" ::: "memory");
}
__device__ __forceinline__ void cp_wait1() {
    asm volatile("cp.async.wait_group 1;" ::: "memory");
}
__device__ __forceinline__ void cp_wait0() {
    asm volatile("cp.async.wait_group 0;" ::: "memory");
}

// sorted top-3 insert (strict >, so earliest index wins ties)
__device__ __forceinline__ void ins3(float* v, int* ix, float s, int k) {
    if (s > v[2]) {
        if (s > v[1]) {
            v[2] = v[1]; ix[2] = ix[1];
            if (s > v[0]) { v[1] = v[0]; ix[1] = ix[0]; v[0] = s; ix[0] = k; }
            else          { v[1] = s; ix[1] = k; }
        } else { v[2] = s; ix[2] = k; }
    }
}

// ============================================================================
// Kernel 1: codebook prep
// ============================================================================
__global__ void vq_prep(const float* __restrict__ cb) {
    int k = blockIdx.x * 256 + threadIdx.x;
    if (k >= KCODES) return;
    const float* c = cb + k * DIM;
    float s = 0.f;
    #pragma unroll
    for (int j = 0; j < DIM; j++) { float v = c[j]; s += v * v; }
    float n = fmaxf(sqrtf(s), 1e-12f);
    double bd = 0.0;
    #pragma unroll
    for (int j = 0; j < DIM; j++) {
        float a = c[j] / n;
        bd += (double)a * (double)a;
        g_cnf[k * DIM + j] = a;
        g_bh[k * DIM + j]  = __float2half_rn(a);
    }
    g_biasd[k] = 0.5 * bd;
    g_biasf[k] = (float)(0.5 * bd);
}

// ============================================================================
// Kernel 2: GEMM + argmax + rescue + outputs
// ============================================================================
__global__ void __launch_bounds__(256, 2)
vq_main(const float* __restrict__ x, const float* __restrict__ cb,
        float* __restrict__ out) {
    extern __shared__ char smem[];
    const uint32_t sb = smem_u32(smem);
    const int tid  = threadIdx.x;
    const int wid  = tid >> 5;
    const int lane = tid & 31;
    const int row0 = blockIdx.x * 128;

    float* xs   = (float*)(smem + SM_XS);     // stride 68 floats
    float* bsm  = (float*)(smem + SM_BIAS);
    float* rnsm = (float*)(smem + SM_RN);
    int*   cand = (int*)(smem + SM_CAND);
    int*   list = (int*)(smem + SM_LIST);
    int*   cnt  = (int*)(smem + SM_CNT);
    int*   isw  = (int*)(smem + SM_ISW);
    float* red  = (float*)(smem + SM_RED);

    if (tid == 0) *cnt = 0;

    // ---- stage x tile ----
    {
        const float4* x4 = (const float4*)(x + (size_t)row0 * DIM);
        #pragma unroll
        for (int i = 0; i < 8; i++) {
            int g = tid + i * 256;            // 2048 float4
            float4 v = x4[g];
            int r = g >> 4, c4 = g & 15;
            float* d = xs + r * 68 + c4 * 4;
            d[0] = v.x; d[1] = v.y; d[2] = v.z; d[3] = v.w;
        }
        #pragma unroll
        for (int i = 0; i < 4; i++) { int g = tid + i * 256; bsm[g] = g_biasf[g]; }
    }

    // ---- prefetch B chunks 0,1 (cp.async; independent of smem x) ----
    const __half* bh = g_bh;
    #pragma unroll
    for (int pc = 0; pc < 2; pc++) {
        #pragma unroll
        for (int i = 0; i < 4; i++) {
            int idx = tid + i * 256;          // 0..1023
            int r = idx >> 3, seg = idx & 7;
            cp16(sb + SM_B + pc * 18432 + r * 144 + seg * 16,
                 bh + ((size_t)(pc * 128 + r)) * 64 + seg * 8);
        }
        cp_commit();
    }
    __syncthreads();

    // ---- normalize rows -> fp16 A (144B stride, conflict-free 4g+c LDS) ----
    if (tid < 128) {
        int r = tid;
        float s = 0.f;
        #pragma unroll
        for (int j = 0; j < DIM; j++) { float v = xs[r * 68 + j]; s += v * v; }
        float n = fmaxf(sqrtf(s), 1e-12f);
        rnsm[r] = n;
        __half2* arow = (__half2*)(smem + SM_A + r * 144);
        #pragma unroll
        for (int j2 = 0; j2 < 32; j2++) {
            float a0 = xs[r * 68 + 2 * j2]     / n;
            float a1 = xs[r * 68 + 2 * j2 + 1] / n;
            arow[j2] = __halves2half2(__float2half_rn(a0), __float2half_rn(a1));
        }
    }
    __syncthreads();

    // ---- load A fragments (persist in registers) ----
    const uint32_t* Ap = (const uint32_t*)(smem + SM_A);
    const int g = lane >> 2, c = lane & 3;
    uint32_t afr[4][4];
    {
        int Rb = wid * 16;
        #pragma unroll
        for (int ks = 0; ks < 4; ks++) {
            afr[ks][0] = Ap[(Rb + g)     * 36 + ks * 8 + c];
            afr[ks][1] = Ap[(Rb + 8 + g) * 36 + ks * 8 + c];
            afr[ks][2] = Ap[(Rb + g)     * 36 + ks * 8 + 4 + c];
            afr[ks][3] = Ap[(Rb + 8 + g) * 36 + ks * 8 + 4 + c];
        }
    }

    // ---- main loop: 8 chunks of 128 codes, double-buffered ----
    float v0[3] = {-1e30f, -1e30f, -1e30f}, v1[3] = {-1e30f, -1e30f, -1e30f};
    int   i0[3] = {0, 0, 0},                i1[3] = {0, 0, 0};

    for (int ch = 0; ch < 8; ch++) {
        if (ch == 7) cp_wait0(); else cp_wait1();
        __syncthreads();
        const uint32_t* Bp = (const uint32_t*)(smem + SM_B + (ch & 1) * 18432);
        int cbase = ch * 128;

        #pragma unroll
        for (int nb = 0; nb < 16; nb += 2) {
            uint32_t b0a[4], b1a[4], b0b[4], b1b[4];
            #pragma unroll
            for (int ks = 0; ks < 4; ks++) {
                int ra = (nb * 8 + g) * 36 + ks * 8 + c;
                int rb = ((nb + 1) * 8 + g) * 36 + ks * 8 + c;
                b0a[ks] = Bp[ra];     b1a[ks] = Bp[ra + 4];
                b0b[ks] = Bp[rb];     b1b[ks] = Bp[rb + 4];
            }
            float acc0[4] = {0.f, 0.f, 0.f, 0.f};
            float acc1[4] = {0.f, 0.f, 0.f, 0.f};
            #pragma unroll
            for (int ks = 0; ks < 4; ks++) {
                mma16816(acc0, afr[ks], b0a[ks], b1a[ks]);
                mma16816(acc1, afr[ks], b0b[ks], b1b[ks]);
            }
            // epilogue: scores = acc - bias
            int col0 = cbase + nb * 8 + 2 * c;
            float2 bb0 = *(const float2*)(bsm + col0);
            float2 bb1 = *(const float2*)(bsm + col0 + 8);
            ins3(v0, i0, acc0[0] - bb0.x, col0);
            ins3(v0, i0, acc0[1] - bb0.y, col0 + 1);
            ins3(v1, i1, acc0[2] - bb0.x, col0);
            ins3(v1, i1, acc0[3] - bb0.y, col0 + 1);
            ins3(v0, i0, acc1[0] - bb1.x, col0 + 8);
            ins3(v0, i0, acc1[1] - bb1.y, col0 + 9);
            ins3(v1, i1, acc1[2] - bb1.x, col0 + 8);
            ins3(v1, i1, acc1[3] - bb1.y, col0 + 9);
        }
        __syncthreads();
        if (ch < 6) {   // prefetch chunk ch+2 into freed buffer
            int pc = ch + 2;
            #pragma unroll
            for (int i = 0; i < 4; i++) {
                int idx = tid + i * 256;
                int r = idx >> 3, seg = idx & 7;
                cp16(sb + SM_B + (pc & 1) * 18432 + r * 144 + seg * 16,
                     bh + ((size_t)(pc * 128 + r)) * 64 + seg * 8);
            }
            cp_commit();
        }
    }

    // ---- quad merge: row best / margin / candidate dump ----
    #pragma unroll
    for (int h = 0; h < 2; h++) {
        float* v = h ? v1 : v0;
        int*   ixv = h ? i1 : i0;
        int row = wid * 16 + 8 * h + g;
        float bs = v[0]; int bi = ixv[0];
        #pragma unroll
        for (int off = 1; off <= 2; off <<= 1) {
            float os = __shfl_xor_sync(0xffffffffu, bs, off);
            int   oi = __shfl_xor_sync(0xffffffffu, bi, off);
            if (os > bs || (os == bs && oi < bi)) { bs = os; bi = oi; }
        }
        float s2 = (ixv[0] == bi) ? v[1] : v[0];
        #pragma unroll
        for (int off = 1; off <= 2; off <<= 1)
            s2 = fmaxf(s2, __shfl_xor_sync(0xffffffffu, s2, off));
        #pragma unroll
        for (int j = 0; j < 3; j++) cand[row * 12 + 3 * c + j] = ixv[j];
        if (c == 0) {
            isw[row] = bi;
            if (bs - s2 < THRESH) { int p = atomicAdd(cnt, 1); list[p] = row; }
        }
    }
    __syncthreads();

    // ---- fp64 rescue of tight rows (12 candidates each) ----
    int nflag = *cnt;
    for (int e = wid; e < nflag; e += 8) {
        int row = list[e];
        double sc = -1e300; int kk = 0x7fffffff;
        if (lane < 12) {
            kk = cand[row * 12 + lane];
            float rn = rnsm[row];
            const float* cp = g_cnf + (size_t)kk * 64;
            const float* xr = xs + row * 68;
            double a0 = 0, a1 = 0, a2 = 0, a3 = 0;
            #pragma unroll
            for (int j = 0; j < 64; j += 4) {
                a0 += (double)(xr[j]     / rn) * (double)cp[j];
                a1 += (double)(xr[j + 1] / rn) * (double)cp[j + 1];
                a2 += (double)(xr[j + 2] / rn) * (double)cp[j + 2];
                a3 += (double)(xr[j + 3] / rn) * (double)cp[j + 3];
            }
            sc = ((a0 + a1) + (a2 + a3)) - g_biasd[kk];
        }
        #pragma unroll
        for (int off = 1; off <= 8; off <<= 1) {
            double os = __shfl_xor_sync(0xffffffffu, sc, off);
            int    oi = __shfl_xor_sync(0xffffffffu, kk, off);
            if (os > sc || (os == sc && oi < kk)) { sc = os; kk = oi; }
        }
        if (lane == 0) isw[row] = kk;
    }
    __syncthreads();

    // ---- outputs: STE quantized + indices + partial SSE ----
    float sse = 0.f;
    #pragma unroll
    for (int i = 0; i < 32; i++) {
        int e = tid + i * 256;                 // 8192 elements
        int r = e >> 6, cc = e & 63;
        int k = isw[r];
        float q  = cb[(size_t)k * DIM + cc];
        float xv = xs[r * 68 + cc];
        float d  = q - xv;
        sse += d * d;
        out[(size_t)(row0 + r) * DIM + cc] = xv + d;   // x + sg(q - x)
    }
    if (tid < 128) out[(size_t)NQ + 2 + row0 + tid] = (float)isw[tid];

    #pragma unroll
    for (int o = 16; o > 0; o >>= 1) sse += __shfl_xor_sync(0xffffffffu, sse, o);
    if (lane == 0) red[wid] = sse;
    __syncthreads();
    if (tid == 0) {
        float t = 0.f;
        #pragma unroll
        for (int w = 0; w < 8; w++) t += red[w];
        g_partials[blockIdx.x] = t;
    }
}

// ============================================================================
// Kernel 3: reduce partials -> both losses
// ============================================================================
__global__ void vq_fin(float* __restrict__ out) {
    __shared__ float red[8];
    int tid = threadIdx.x;
    float s = 0.f;
    #pragma unroll
    for (int i = 0; i < 8; i++) s += g_partials[tid + i * 256];
    #pragma unroll
    for (int o = 16; o > 0; o >>= 1) s += __shfl_xor_sync(0xffffffffu, s, o);
    if ((tid & 31) == 0) red[tid >> 5] = s;
    __syncthreads();
    if (tid == 0) {
        float t = 0.f;
        #pragma unroll
        for (int w = 0; w < 8; w++) t += red[w];
        float loss = t / 16777216.0f;
        out[NQ]     = loss;   // codebook_loss
        out[NQ + 1] = loss;   // commitment_loss
    }
}

// ============================================================================
extern "C" void kernel_launch(void* const* d_in, const int* in_sizes, int n_in,
                              void* d_out, int out_size) {
    const float* x;
    const float* cb;
    if (in_sizes[0] == NROWS * DIM) {
        x  = (const float*)d_in[0];
        cb = (const float*)d_in[1];
    } else {
        x  = (const float*)d_in[1];
        cb = (const float*)d_in[0];
    }
    float* out = (float*)d_out;

    cudaFuncSetAttribute(vq_main, cudaFuncAttributeMaxDynamicSharedMemorySize, SM_TOTAL);

    vq_prep<<<4, 256>>>(cb);
    vq_main<<<TILES, 256, SM_TOTAL>>>(x, cb, out);
    vq_fin<<<1, 256>>>(out);
}